// round 16
// baseline (speedup 1.0000x reference)
#include <cuda_runtime.h>
#include <math.h>
#include <stdint.h>

// ---------------- problem constants ----------------
#define NN 768
#define NTILES 6              // 768 / 128
#define LOG2E 1.4426950408889634f

// ---------------- smem layout (bytes) ----------------
#define OB_A    1024               // A staging: 128 rows x 128B, hi + lo planes (32KB)
#define OB_W1   (OB_A + 32768)     // we1: hi 8192B + lo 8192B
#define OB_WX0  (OB_W1 + 16384)    // wx0: hi only
#define OB_WX1  (OB_WX0 + 8192)    // wx1: hi only
#define OB_MISC (OB_WX1 + 8192)
// misc float indices
#define MF_WE0H 0      // we0 rows 0..3 [4][64]
#define MF_WX2  256    // wx2 raw [64][4]
#define MF_WINF 512
#define MF_BE1  576
#define MF_BX0  640
#define MF_BX1  704
#define MF_BX2  768    // [4]
#define MF_C    772    // [64]
#define MISC_FLOATS 840
#define SMEM_BYTES (OB_MISC + MISC_FLOATS*4 + 64)

// scratch (no cudaMalloc allowed)
__device__ float g_G[NN * 64];   // hc_j @ We0[4:84] + be0
__device__ float g_C[NN * 64];   // hc_i @ We0[84:164]
__device__ float g_mi[NN * 64];

// ---------------- helpers ----------------
__device__ __forceinline__ uint32_t smem_u32(const void* p) {
    uint32_t a;
    asm("{ .reg .u64 t; cvta.to.shared.u64 t, %1; cvt.u32.u64 %0, t; }"
        : "=r"(a) : "l"(p));
    return a;
}
__device__ __forceinline__ float rcpf_(float x) {
    float r; asm("rcp.approx.ftz.f32 %0, %1;" : "=f"(r) : "f"(x)); return r;
}
__device__ __forceinline__ float ex2f_(float x) {
    float r; asm("ex2.approx.ftz.f32 %0, %1;" : "=f"(r) : "f"(x)); return r;
}
__device__ __forceinline__ float rsqf_(float x) {
    float r; asm("rsqrt.approx.ftz.f32 %0, %1;" : "=f"(r) : "f"(x)); return r;
}
__device__ __forceinline__ float sigmoidf_(float x) { return rcpf_(1.0f + ex2f_(-x * LOG2E)); }
__device__ __forceinline__ float siluf_(float x)    { return x * rcpf_(1.0f + ex2f_(-x * LOG2E)); }

// pack (lo,hi) f32 -> bf16x2; low 16 bits = first arg
__device__ __forceinline__ uint32_t cvtpk(float lo, float hi) {
    uint32_t d;
    asm("cvt.rn.bf16x2.f32 %0, %1, %2;" : "=r"(d) : "f"(hi), "f"(lo));
    return d;
}
__device__ __forceinline__ float bf_lo_f32(uint32_t d) { return __uint_as_float(d << 16); }
__device__ __forceinline__ float bf_hi_f32(uint32_t d) { return __uint_as_float(d & 0xFFFF0000u); }

// row-swizzled byte offset inside a [row][128B] tile (16B-chunk XOR)
#define SWZ(row, kb) ((uint32_t)((row) * 128 + ((kb) ^ (((row) & 7) << 4))))

__device__ __forceinline__ void ldsm4(uint32_t* r, uint32_t addr) {
    asm volatile("ldmatrix.sync.aligned.m8n8.x4.shared.b16 {%0,%1,%2,%3}, [%4];"
        : "=r"(r[0]), "=r"(r[1]), "=r"(r[2]), "=r"(r[3]) : "r"(addr));
}
__device__ __forceinline__ void mma16816(float* c, const uint32_t* a, const uint32_t* b) {
    asm volatile("mma.sync.aligned.m16n8k16.row.col.f32.bf16.bf16.f32 "
        "{%0,%1,%2,%3}, {%4,%5,%6,%7}, {%8,%9}, {%0,%1,%2,%3};"
        : "+f"(c[0]), "+f"(c[1]), "+f"(c[2]), "+f"(c[3])
        : "r"(a[0]), "r"(a[1]), "r"(a[2]), "r"(a[3]), "r"(b[0]), "r"(b[1]));
}
#define STS128(a, r0, r1, r2, r3) \
    asm volatile("st.shared.v4.b32 [%0], {%1, %2, %3, %4};" :: "r"(a), "r"(r0), "r"(r1), "r"(r2), "r"(r3) : "memory")
#define STS32(a, r0) \
    asm volatile("st.shared.b32 [%0], %1;" :: "r"(a), "r"(r0) : "memory")

// ---------------- prep: G[m]=hc_m@We0[4:84]+be0, C[m]=hc_m@We0[84:164] ----------------
__global__ void prep_kernel(const float* __restrict__ x, const float* __restrict__ h,
                            const float* __restrict__ we0, const float* __restrict__ be0) {
    __shared__ float hc[80];
    const int m = blockIdx.x;
    const int t = threadIdx.x;  // 128
    if (t < 64) {
        hc[t] = h[m * 64 + t];
    } else if (t < 80) {
        int p = t - 64;
        int a = p >> 2, b = p & 3;
        const float* xr = x + m * 12;
        float dx = xr[b * 3 + 0] - xr[a * 3 + 0];
        float dy = xr[b * 3 + 1] - xr[a * 3 + 1];
        float dz = xr[b * 3 + 2] - xr[a * 3 + 2];
        hc[t] = dx * dx + dy * dy + dz * dz;
    }
    __syncthreads();
    const int o = t & 63;
    const float* W = we0 + ((t < 64) ? 4 * 64 : 84 * 64);
    float a = (t < 64) ? be0[o] : 0.0f;
#pragma unroll 8
    for (int k = 0; k < 80; k++) a += hc[k] * W[k * 64 + o];
    if (t < 64) g_G[m * 64 + o] = a;
    else        g_C[m * 64 + o] = a;
}

// store W[k][o] (64x64 f32) as [o][k] bf16 hi(+lo) planes, swizzled
__device__ __forceinline__ void fill_wtile_split(uint32_t sb, uint32_t wof,
                                                 const float* __restrict__ W, int tid) {
    for (int t = tid; t < 2048; t += 256) {
        int o = t >> 5;
        int kp = (t & 31) * 2;
        float v0 = __ldg(W + kp * 64 + o);
        float v1 = __ldg(W + (kp + 1) * 64 + o);
        uint32_t hp = cvtpk(v0, v1);
        uint32_t lp = cvtpk(v0 - bf_lo_f32(hp), v1 - bf_hi_f32(hp));
        uint32_t ub = wof + SWZ(o, kp * 2);
        STS32(sb + ub, hp);
        STS32(sb + ub + 8192, lp);
    }
}
__device__ __forceinline__ void fill_wtile_hi(uint32_t sb, uint32_t wof,
                                              const float* __restrict__ W, int tid) {
    for (int t = tid; t < 2048; t += 256) {
        int o = t >> 5;
        int kp = (t & 31) * 2;
        float v0 = __ldg(W + kp * 64 + o);
        float v1 = __ldg(W + (kp + 1) * 64 + o);
        STS32(sb + wof + SWZ(o, kp * 2), cvtpk(v0, v1));
    }
}

// 3-split GEMM (GEMM1): acc[8][4] += A(16x64 m-tile, hi+lo) @ W(hi+lo)
__device__ __forceinline__ void gemm_split(float acc[8][4],
                                           const uint32_t Ah[4][4],
                                           const uint32_t Al[4][4],
                                           uint32_t wbase, int lane) {
    const uint32_t nrow_lo = (lane & 7) + ((lane & 16) >> 1);
    const uint32_t kb_off = (lane & 8) << 1;
#pragma unroll
    for (int kt = 0; kt < 4; kt++) {
#pragma unroll
        for (int ntp = 0; ntp < 4; ntp++) {
            uint32_t ad = wbase + SWZ(ntp * 16 + nrow_lo, kt * 32 + kb_off);
            uint32_t Bh[4], Bl[4];
            ldsm4(Bh, ad);
            ldsm4(Bl, ad + 8192);
            mma16816(acc[2 * ntp],     Ah[kt], Bh);
            mma16816(acc[2 * ntp],     Ah[kt], Bl);
            mma16816(acc[2 * ntp],     Al[kt], Bh);
            mma16816(acc[2 * ntp + 1], Ah[kt], Bh + 2);
            mma16816(acc[2 * ntp + 1], Ah[kt], Bl + 2);
            mma16816(acc[2 * ntp + 1], Al[kt], Bh + 2);
        }
    }
}

// hi-only GEMM (GEMM2/3): acc[8][4] += A(hi) @ W(hi)
__device__ __forceinline__ void gemm_hi(float acc[8][4],
                                        const uint32_t Ah[4][4],
                                        uint32_t wbase, int lane) {
    const uint32_t nrow_lo = (lane & 7) + ((lane & 16) >> 1);
    const uint32_t kb_off = (lane & 8) << 1;
#pragma unroll
    for (int kt = 0; kt < 4; kt++) {
#pragma unroll
        for (int ntp = 0; ntp < 4; ntp++) {
            uint32_t Bh[4];
            ldsm4(Bh, wbase + SWZ(ntp * 16 + nrow_lo, kt * 32 + kb_off));
            mma16816(acc[2 * ntp],     Ah[kt], Bh);
            mma16816(acc[2 * ntp + 1], Ah[kt], Bh + 2);
        }
    }
}

// bias + silu in place on acc
__device__ __forceinline__ void bias_silu(float a[8][4], const float* bias, int lr) {
#pragma unroll
    for (int nt = 0; nt < 8; nt++) {
        float2 b = *(const float2*)(bias + nt * 8 + lr * 2);
        a[nt][0] = siluf_(a[nt][0] + b.x);
        a[nt][1] = siluf_(a[nt][1] + b.y);
        a[nt][2] = siluf_(a[nt][2] + b.x);
        a[nt][3] = siluf_(a[nt][3] + b.y);
    }
}

// D fragments -> hi-only A fragments for next GEMM (pure registers)
__device__ __forceinline__ void pack_frags_hi(const float a[8][4], uint32_t Ah[4][4]) {
#pragma unroll
    for (int kt = 0; kt < 4; kt++) {
        const float* p0 = a[2 * kt];
        const float* p1 = a[2 * kt + 1];
        Ah[kt][0] = cvtpk(p0[0], p0[1]);
        Ah[kt][1] = cvtpk(p0[2], p0[3]);
        Ah[kt][2] = cvtpk(p1[0], p1[1]);
        Ah[kt][3] = cvtpk(p1[2], p1[3]);
    }
}

// ---------------- main fused pair kernel (256 threads, 8 warps) ----------------
__global__ void __launch_bounds__(256, 2)
egcl_main(const float* __restrict__ x,
          const float* __restrict__ we0,
          const float* __restrict__ we1, const float* __restrict__ be1,
          const float* __restrict__ winf, const float* __restrict__ binf,
          const float* __restrict__ wx0, const float* __restrict__ bx0,
          const float* __restrict__ wx1, const float* __restrict__ bx1,
          const float* __restrict__ wx2, const float* __restrict__ bx2,
          float* __restrict__ out) {
    extern __shared__ char smem[];
    const uint32_t sb = smem_u32(smem);
    float* msc = (float*)(smem + OB_MISC);
    const int i = blockIdx.x;
    const int tid = threadIdx.x;   // 256
    const int lane = tid & 31;
    const int wid = tid >> 5;      // 0..7
    const int lq = lane >> 2;      // 0..7
    const int lr = lane & 3;       // 0..3
    const int rb = wid * 16;       // warp's m-tile row base in 128-row tile

    fill_wtile_split(sb, OB_W1, we1, tid);
    fill_wtile_hi(sb, OB_WX0, wx0, tid);
    fill_wtile_hi(sb, OB_WX1, wx1, tid);
    if (tid < 128) {
        msc[MF_WE0H + tid]       = we0[tid];
        msc[MF_WE0H + 128 + tid] = we0[128 + tid];
        msc[MF_WX2 + tid]        = wx2[tid];
        msc[MF_WX2 + 128 + tid]  = wx2[128 + tid];
    }
    if (tid < 64) {
        msc[MF_WINF + tid] = winf[tid];
        msc[MF_BE1 + tid]  = be1[tid];
        msc[MF_BX0 + tid]  = bx0[tid];
        msc[MF_BX1 + tid]  = bx1[tid];
        msc[MF_C + tid]    = g_C[i * 64 + tid];
    }
    if (tid < 4) msc[MF_BX2 + tid] = bx2[tid];

    const float rbinf = __ldg(binf);
    float xi[12];
#pragma unroll
    for (int t = 0; t < 12; t++) xi[t] = __ldg(x + i * 12 + t);
    __syncthreads();

    float acc_mi[8][2];
#pragma unroll
    for (int nt = 0; nt < 8; nt++) { acc_mi[nt][0] = 0.f; acc_mi[nt][1] = 0.f; }
    float sh0 = 0.f, sh1 = 0.f, sh2 = 0.f;

    for (int tile = 0; tile < NTILES; tile++) {
        // ---- Phase A: row = tid&127; two threads per row, 4 chunks each ----
        {
            const int row = tid & 127;
            const int cg = tid >> 7;           // 0 or 1: chunks cg*4 .. cg*4+3
            const int j2 = tile * 128 + row;
            const float4* xr = (const float4*)(x + j2 * 12);
            float4 f0 = __ldg(xr), f1 = __ldg(xr + 1), f2 = __ldg(xr + 2);
            float xj[12] = {f0.x, f0.y, f0.z, f0.w, f1.x, f1.y, f1.z, f1.w,
                            f2.x, f2.y, f2.z, f2.w};
            float sq[4];
#pragma unroll
            for (int hh = 0; hh < 4; hh++) {
                float dx = xj[hh * 3 + 0] - xi[hh * 3 + 0];
                float dy = xj[hh * 3 + 1] - xi[hh * 3 + 1];
                float dz = xj[hh * 3 + 2] - xi[hh * 3 + 2];
                sq[hh] = dx * dx + dy * dy + dz * dz;
            }
            const float4* gg = (const float4*)(g_G + j2 * 64);
            const uint32_t swz = (uint32_t)((row & 7) << 4);
#pragma unroll
            for (int cc = 0; cc < 4; cc++) {
                int c = cg * 4 + cc;
                float4 gA = __ldg(gg + 2 * c);
                float4 gB = __ldg(gg + 2 * c + 1);
                float v[8] = {gA.x, gA.y, gA.z, gA.w, gB.x, gB.y, gB.z, gB.w};
#pragma unroll
                for (int p = 0; p < 8; p++) {
                    int o = c * 8 + p;
                    float pre = v[p] + msc[MF_C + o];
#pragma unroll
                    for (int hh = 0; hh < 4; hh++)
                        pre += sq[hh] * msc[MF_WE0H + hh * 64 + o];
                    v[p] = siluf_(pre);
                }
                uint32_t hi[4], lo[4];
#pragma unroll
                for (int p = 0; p < 4; p++) {
                    uint32_t hw = cvtpk(v[2 * p], v[2 * p + 1]);
                    hi[p] = hw;
                    lo[p] = cvtpk(v[2 * p] - bf_lo_f32(hw), v[2 * p + 1] - bf_hi_f32(hw));
                }
                uint32_t ad = sb + OB_A + row * 128 + (((uint32_t)(c * 16)) ^ swz);
                STS128(ad, hi[0], hi[1], hi[2], hi[3]);
                STS128(ad + 16384, lo[0], lo[1], lo[2], lo[3]);
            }
        }
        __syncthreads();

        // ---- load A fragments for GEMM1 (warp's 16-row m-tile) ----
        uint32_t Ah[4][4], Al[4][4];
        {
            const uint32_t rlo = (uint32_t)(lane & 15);
            const uint32_t khalf = (uint32_t)(lane & 16);
#pragma unroll
            for (int kt = 0; kt < 4; kt++) {
                uint32_t ad = sb + OB_A + SWZ(rb + rlo, kt * 32 + khalf);
                ldsm4(Ah[kt], ad);
                ldsm4(Al[kt], ad + 16384);
            }
        }
        __syncthreads();   // A-staging reads done before next tile's phase A

        float acc[8][4];
#pragma unroll
        for (int nt = 0; nt < 8; nt++)
#pragma unroll
            for (int q = 0; q < 4; q++) acc[nt][q] = 0.f;

        // ---- GEMM1 (3-split): m_ij = silu(A @ We1 + be1); fused phi_inf / e / m_i ----
        gemm_split(acc, Ah, Al, sb + OB_W1, lane);
        bias_silu(acc, msc + MF_BE1, lr);
        {
            float d0 = 0.f, d1 = 0.f;
#pragma unroll
            for (int nt = 0; nt < 8; nt++) {
                float2 wf = *(const float2*)(msc + MF_WINF + nt * 8 + lr * 2);
                d0 += acc[nt][0] * wf.x + acc[nt][1] * wf.y;
                d1 += acc[nt][2] * wf.x + acc[nt][3] * wf.y;
            }
            d0 += __shfl_xor_sync(0xffffffffu, d0, 1);
            d0 += __shfl_xor_sync(0xffffffffu, d0, 2);
            d1 += __shfl_xor_sync(0xffffffffu, d1, 1);
            d1 += __shfl_xor_sync(0xffffffffu, d1, 2);
            int j0 = tile * 128 + rb + lq;
            float e0 = sigmoidf_(d0 + rbinf);
            float e1 = sigmoidf_(d1 + rbinf);
            if (j0 == i) e0 = 0.f;
            if (j0 + 8 == i) e1 = 0.f;
#pragma unroll
            for (int nt = 0; nt < 8; nt++) {
                acc_mi[nt][0] += e0 * acc[nt][0] + e1 * acc[nt][2];
                acc_mi[nt][1] += e0 * acc[nt][1] + e1 * acc[nt][3];
            }
        }
        pack_frags_hi(acc, Ah);

        // ---- GEMM2 (hi-only): t0 = silu(m_ij @ Wx0 + bx0) ----
#pragma unroll
        for (int nt = 0; nt < 8; nt++)
#pragma unroll
            for (int q = 0; q < 4; q++) acc[nt][q] = 0.f;
        gemm_hi(acc, Ah, sb + OB_WX0, lane);
        bias_silu(acc, msc + MF_BX0, lr);
        pack_frags_hi(acc, Ah);

        // ---- GEMM3 (hi-only): t1 = silu(t0 @ Wx1 + bx1); phi_x2 + shift ----
#pragma unroll
        for (int nt = 0; nt < 8; nt++)
#pragma unroll
            for (int q = 0; q < 4; q++) acc[nt][q] = 0.f;
        gemm_hi(acc, Ah, sb + OB_WX1, lane);
        bias_silu(acc, msc + MF_BX1, lr);
        {
            float part[2][4];
#pragma unroll
            for (int r = 0; r < 2; r++)
#pragma unroll
                for (int hh = 0; hh < 4; hh++) part[r][hh] = 0.f;
#pragma unroll
            for (int nt = 0; nt < 8; nt++)
#pragma unroll
                for (int qp = 0; qp < 2; qp++) {
                    int c = nt * 8 + lr * 2 + qp;
                    float4 w4 = *(const float4*)(msc + MF_WX2 + c * 4);
                    float v0 = acc[nt][qp];
                    float v1 = acc[nt][2 + qp];
                    part[0][0] += v0 * w4.x;  part[0][1] += v0 * w4.y;
                    part[0][2] += v0 * w4.z;  part[0][3] += v0 * w4.w;
                    part[1][0] += v1 * w4.x;  part[1][1] += v1 * w4.y;
                    part[1][2] += v1 * w4.z;  part[1][3] += v1 * w4.w;
                }
#pragma unroll
            for (int r = 0; r < 2; r++)
#pragma unroll
                for (int hh = 0; hh < 4; hh++) {
                    part[r][hh] += __shfl_xor_sync(0xffffffffu, part[r][hh], 1);
                    part[r][hh] += __shfl_xor_sync(0xffffffffu, part[r][hh], 2);
                }
            const float bxh = msc[MF_BX2 + lr];
            const float xih0 = xi[lr * 3 + 0], xih1 = xi[lr * 3 + 1], xih2 = xi[lr * 3 + 2];
#pragma unroll
            for (int half = 0; half < 2; half++) {
                int j = tile * 128 + rb + lq + half * 8;
                float d = part[half][lr] + bxh;
                const float* xa = x + j * 12 + lr * 3;
                float dx = __ldg(xa + 0) - xih0;
                float dy = __ldg(xa + 1) - xih1;
                float dz = __ldg(xa + 2) - xih2;
                float sqn = dx * dx + dy * dy + dz * dz;
                float sp = (sqn == 0.f) ? 1.f : sqn;
                float nrm = sp * rsqf_(sp) + 1.f;   // sqrt(sp)+1
                float cc = d * rcpf_(nrm);
                if (j == i) cc = 0.f;
                sh0 += cc * dx;
                sh1 += cc * dy;
                sh2 += cc * dz;
            }
        }
    }

    // ---- reductions (reuse A staging smem) ----
    float* st = (float*)(smem + OB_A);
    __syncthreads();
#pragma unroll
    for (int nt = 0; nt < 8; nt++) {
        st[tid * 16 + nt * 2 + 0] = acc_mi[nt][0];
        st[tid * 16 + nt * 2 + 1] = acc_mi[nt][1];
    }
    __syncthreads();
    if (tid < 64) {
        // column = tid: nt = tid>>3, lr-part = (tid&7)>>1, q = tid&1;
        // sum over all 64 threads with that lr: T = b*4 + lr, b in 0..63
        int nt = tid >> 3, lrr = (tid & 7) >> 1, q = tid & 1;
        float s = 0.f;
#pragma unroll 8
        for (int b = 0; b < 64; b++) s += st[(b * 4 + lrr) * 16 + nt * 2 + q];
        g_mi[i * 64 + tid] = s * (1.0f / sqrtf(767.0f));
    }
    __syncthreads();
    st[tid * 3 + 0] = sh0;
    st[tid * 3 + 1] = sh1;
    st[tid * 3 + 2] = sh2;
    __syncthreads();
    if (tid < 12) {
        int hh = tid / 3, d = tid - hh * 3;
        float s = 0.f;
#pragma unroll 8
        for (int b = 0; b < 64; b++) s += st[(b * 4 + hh) * 3 + d];
        out[i * 12 + tid] = xi[tid] + s * (1.0f / 767.0f);
    }
}

// ---------------- phi_h per node ----------------
__global__ void phi_h_kernel(const float* __restrict__ h,
                             const float* __restrict__ w0, const float* __restrict__ b0,
                             const float* __restrict__ w1, const float* __restrict__ b1,
                             const float* __restrict__ w2, const float* __restrict__ b2,
                             float* __restrict__ out) {
    __shared__ float in1[128], t0[64], t1[64];
    const int i = blockIdx.x;
    const int o = threadIdx.x;  // 64
    in1[o] = g_mi[i * 64 + o];
    in1[64 + o] = h[i * 64 + o];
    __syncthreads();
    float a = b0[o];
#pragma unroll 4
    for (int k = 0; k < 128; k++) a += in1[k] * w0[k * 64 + o];
    t0[o] = siluf_(a);
    __syncthreads();
    a = b1[o];
#pragma unroll 4
    for (int k = 0; k < 64; k++) a += t0[k] * w1[k * 64 + o];
    t1[o] = siluf_(a);
    __syncthreads();
    a = b2[o];
#pragma unroll 4
    for (int k = 0; k < 64; k++) a += t1[k] * w2[k * 64 + o];
    out[NN * 12 + i * 64 + o] = h[i * 64 + o] + a;
}

extern "C" void kernel_launch(void* const* d_in, const int* in_sizes, int n_in,
                              void* d_out, int out_size) {
    const float* x    = (const float*)d_in[0];
    const float* h    = (const float*)d_in[1];
    const float* we0  = (const float*)d_in[2];
    const float* be0  = (const float*)d_in[3];
    const float* we1  = (const float*)d_in[4];
    const float* be1  = (const float*)d_in[5];
    const float* winf = (const float*)d_in[6];
    const float* binf = (const float*)d_in[7];
    const float* wx0  = (const float*)d_in[8];
    const float* bx0  = (const float*)d_in[9];
    const float* wx1  = (const float*)d_in[10];
    const float* bx1  = (const float*)d_in[11];
    const float* wx2  = (const float*)d_in[12];
    const float* bx2  = (const float*)d_in[13];
    const float* wh0  = (const float*)d_in[14];
    const float* bh0  = (const float*)d_in[15];
    const float* wh1  = (const float*)d_in[16];
    const float* bh1  = (const float*)d_in[17];
    const float* wh2  = (const float*)d_in[18];
    const float* bh2  = (const float*)d_in[19];
    float* out = (float*)d_out;

    cudaFuncSetAttribute(egcl_main, cudaFuncAttributeMaxDynamicSharedMemorySize, SMEM_BYTES);

    prep_kernel<<<NN, 128>>>(x, h, we0, be0);
    egcl_main<<<NN, 256, SMEM_BYTES>>>(x, we0, we1, be1, winf, binf,
                                       wx0, bx0, wx1, bx1, wx2, bx2, out);
    phi_h_kernel<<<NN, 64>>>(h, wh0, bh0, wh1, bh1, wh2, bh2, out);
}